// round 11
// baseline (speedup 1.0000x reference)
#include <cuda_runtime.h>
#include <cuda_bf16.h>
#include <cstdint>

#define BB 4
#define SS 2048
#define DD 1024
#define HH 16
#define HDIM 64
#define MTOT (BB * SS)   // 8192

// ---------------------------------------------------------------------------
// Device scratch (static globals: no runtime allocation)
// ---------------------------------------------------------------------------
__device__ __nv_bfloat16 g_xhi[(size_t)3 * MTOT * DD];
__device__ __nv_bfloat16 g_xlo[(size_t)3 * MTOT * DD];
__device__ __nv_bfloat16 g_whi[(size_t)3 * DD * DD];
__device__ __nv_bfloat16 g_wlo[(size_t)3 * DD * DD];

__device__ __nv_bfloat16 g_qh[(size_t)MTOT * DD];
__device__ __nv_bfloat16 g_ql[(size_t)MTOT * DD];
__device__ __nv_bfloat16 g_kh[(size_t)MTOT * DD];
__device__ __nv_bfloat16 g_kl[(size_t)MTOT * DD];
__device__ __nv_bfloat16 g_vh[(size_t)MTOT * DD];
__device__ __nv_bfloat16 g_vl[(size_t)MTOT * DD];

__device__ unsigned int g_ctr[2];   // work-queue counters: [0]=proj, [1]=attn

// ---------------------------------------------------------------------------
// Helpers
// ---------------------------------------------------------------------------
__device__ __forceinline__ uint32_t smem_u32(const void* p) {
    uint32_t a;
    asm("{ .reg .u64 t; cvta.to.shared.u64 t, %1; cvt.u32.u64 %0, t; }"
        : "=r"(a) : "l"(p));
    return a;
}

__device__ __forceinline__ void bf16_split(float x, uint32_t& h, uint32_t& l) {
    __nv_bfloat16 hb = __float2bfloat16(x);
    __nv_bfloat16 lb = __float2bfloat16(x - __bfloat162float(hb));
    h = (uint32_t)__bfloat16_as_ushort(hb);
    l = (uint32_t)__bfloat16_as_ushort(lb);
}

// Pack (f0 -> low half, f1 -> high half) into bf16x2; also produce the residual pair.
__device__ __forceinline__ uint32_t pack_split2(float f0, float f1, uint32_t& lo) {
    uint32_t hp;
    asm("cvt.rn.bf16x2.f32 %0, %1, %2;" : "=r"(hp) : "f"(f1), "f"(f0));
    float h0 = __bfloat162float(__ushort_as_bfloat16((unsigned short)(hp & 0xffffu)));
    float h1 = __bfloat162float(__ushort_as_bfloat16((unsigned short)(hp >> 16)));
    asm("cvt.rn.bf16x2.f32 %0, %1, %2;" : "=r"(lo) : "f"(f1 - h1), "f"(f0 - h0));
    return hp;
}

__device__ __forceinline__ float ex2(float x) {
    float r;
    asm("ex2.approx.f32 %0, %1;" : "=f"(r) : "f"(x));
    return r;
}

__device__ __forceinline__ void mma16816(float* c, const uint32_t* a,
                                         uint32_t b0, uint32_t b1) {
    asm volatile(
        "mma.sync.aligned.m16n8k16.row.col.f32.bf16.bf16.f32 "
        "{%0,%1,%2,%3}, {%4,%5,%6,%7}, {%8,%9}, {%0,%1,%2,%3};"
        : "+f"(c[0]), "+f"(c[1]), "+f"(c[2]), "+f"(c[3])
        : "r"(a[0]), "r"(a[1]), "r"(a[2]), "r"(a[3]), "r"(b0), "r"(b1));
}

#define LDM4(r, addr)                                                         \
    asm volatile("ldmatrix.sync.aligned.m8n8.x4.shared.b16 {%0,%1,%2,%3}, [%4];" \
                 : "=r"((r)[0]), "=r"((r)[1]), "=r"((r)[2]), "=r"((r)[3])     \
                 : "r"(addr))

#define LDM4T(r, addr)                                                        \
    asm volatile("ldmatrix.sync.aligned.m8n8.x4.trans.shared.b16 {%0,%1,%2,%3}, [%4];" \
                 : "=r"((r)[0]), "=r"((r)[1]), "=r"((r)[2]), "=r"((r)[3])     \
                 : "r"(addr))

#define CP_ASYNC16(saddr, gaddr)                                              \
    asm volatile("cp.async.cg.shared.global [%0], [%1], 16;"                  \
                 :: "r"(saddr), "l"(gaddr))
#define CP_COMMIT() asm volatile("cp.async.commit_group;")
#define CP_WAIT1()  asm volatile("cp.async.wait_group 1;")
#define CP_WAIT0()  asm volatile("cp.async.wait_group 0;")

// ---------------------------------------------------------------------------
// Counter reset (runs before the persistent kernels each launch/replay)
// ---------------------------------------------------------------------------
__global__ void reset_ctrs() {
    g_ctr[0] = 0;
    g_ctr[1] = 0;
}

// ---------------------------------------------------------------------------
// Input converts: fp32 -> bf16 hi/lo
// ---------------------------------------------------------------------------
__global__ __launch_bounds__(256) void convert_x(
    const float* __restrict__ xq, const float* __restrict__ xk, const float* __restrict__ xv)
{
    const float* src = (blockIdx.z == 0) ? xq : (blockIdx.z == 1) ? xk : xv;
    size_t i = ((size_t)blockIdx.x * 256 + threadIdx.x) * 4;
    size_t o = (size_t)blockIdx.z * MTOT * DD + i;
    float4 x = *(const float4*)(src + i);
    uint32_t h0, l0, h1, l1, h2, l2, h3, l3;
    bf16_split(x.x, h0, l0); bf16_split(x.y, h1, l1);
    bf16_split(x.z, h2, l2); bf16_split(x.w, h3, l3);
    uint2 hv, lv;
    hv.x = h0 | (h1 << 16); hv.y = h2 | (h3 << 16);
    lv.x = l0 | (l1 << 16); lv.y = l2 | (l3 << 16);
    *(uint2*)(g_xhi + o) = hv;
    *(uint2*)(g_xlo + o) = lv;
}

__global__ __launch_bounds__(256) void convert_w(
    const float* __restrict__ wq, const float* __restrict__ wk, const float* __restrict__ wv)
{
    const float* src = (blockIdx.z == 0) ? wq : (blockIdx.z == 1) ? wk : wv;
    size_t i = ((size_t)blockIdx.x * 256 + threadIdx.x) * 4;
    size_t o = (size_t)blockIdx.z * DD * DD + i;
    float4 x = *(const float4*)(src + i);
    uint32_t h0, l0, h1, l1, h2, l2, h3, l3;
    bf16_split(x.x, h0, l0); bf16_split(x.y, h1, l1);
    bf16_split(x.z, h2, l2); bf16_split(x.w, h3, l3);
    uint2 hv, lv;
    hv.x = h0 | (h1 << 16); hv.y = h2 | (h3 << 16);
    lv.x = l0 | (l1 << 16); lv.y = l2 | (l3 << 16);
    *(uint2*)(g_whi + o) = hv;
    *(uint2*)(g_wlo + o) = lv;
}

// ---------------------------------------------------------------------------
// bf16x3 projection GEMM: PERSISTENT grid + dynamic work queue.
// 1536 items = which(3) x m-block(64) x n-block(8), m-major for L2 reuse.
// Q output (which==0) pre-scaled by 0.125*log2(e).
// ---------------------------------------------------------------------------
#define PJ_BK 32
#define PJ_NCH (DD / PJ_BK)     // 32
#define PJ_STAGE 32768
#define PJ_SMEM (3 * PJ_STAGE + 16)  // 96KB + item slot
#define PJ_ITEMS 1536
#define PJ_GRID 296

__device__ __forceinline__ void proj_load_stage(
    uint32_t sb, uint32_t stage_off,
    const __nv_bfloat16* __restrict__ Ah, const __nv_bfloat16* __restrict__ Al,
    const __nv_bfloat16* __restrict__ Bh, const __nv_bfloat16* __restrict__ Bl,
    int m0, int n0, int k0, int tid)
{
#pragma unroll
    for (int q = 0; q < 2; q++) {
        const int id = tid * 2 + q;
        const int row = id >> 2;
        const int ch = id & 3;
        const uint32_t so = stage_off + (uint32_t)(row * 64 + ((ch ^ ((row >> 1) & 3)) * 16));
        const size_t ga = (size_t)(m0 + row) * DD + k0 + ch * 8;
        const size_t gb = (size_t)(n0 + row) * DD + k0 + ch * 8;
        CP_ASYNC16(sb + so,          (const void*)(Ah + ga));
        CP_ASYNC16(sb + so + 8192,   (const void*)(Al + ga));
        CP_ASYNC16(sb + so + 16384,  (const void*)(Bh + gb));
        CP_ASYNC16(sb + so + 24576,  (const void*)(Bl + gb));
    }
}

__global__ __launch_bounds__(256, 2) void proj_mma(
    const float* __restrict__ bq, const float* __restrict__ bk, const float* __restrict__ bv)
{
    extern __shared__ char smraw[];
    const uint32_t sb = smem_u32(smraw);
    const uint32_t slot = sb + 3 * PJ_STAGE;          // item broadcast slot

    const int tid = threadIdx.x;
    const int wid = tid >> 5;
    const int lane = tid & 31;
    const int warp_m = wid & 3;
    const int warp_n = wid >> 2;
    const int lrow = lane & 15;
    const int lkh = lane >> 4;
    const int quad = lane >> 2;
    const int tpos = lane & 3;

    for (;;) {
        if (tid == 0) {
            unsigned int it = atomicAdd(&g_ctr[0], 1u);
            asm volatile("st.shared.u32 [%0], %1;" :: "r"(slot), "r"(it));
        }
        __syncthreads();
        unsigned int item;
        asm volatile("ld.shared.u32 %0, [%1];" : "=r"(item) : "r"(slot));
        if (item >= PJ_ITEMS) break;

        const int which = (int)(item >> 9);           // /512
        const int rem = (int)(item & 511);
        const int m0 = (rem >> 3) * 128;
        const int n0 = (rem & 7) * 128;

        const __nv_bfloat16* Ah = g_xhi + (size_t)which * MTOT * DD;
        const __nv_bfloat16* Al = g_xlo + (size_t)which * MTOT * DD;
        const __nv_bfloat16* Bh = g_whi + (size_t)which * DD * DD;
        const __nv_bfloat16* Bl = g_wlo + (size_t)which * DD * DD;
        const float* bias = (which == 0) ? bq : (which == 1) ? bk : bv;
        __nv_bfloat16* Yh = (which == 0) ? g_qh : (which == 1) ? g_kh : g_vh;
        __nv_bfloat16* Yl = (which == 0) ? g_ql : (which == 1) ? g_kl : g_vl;

        float acc[2][8][4];
#pragma unroll
        for (int t = 0; t < 2; t++)
#pragma unroll
            for (int j = 0; j < 8; j++)
#pragma unroll
                for (int c = 0; c < 4; c++) acc[t][j][c] = 0.0f;

        // Prologue: 2 stages in flight (buffers 0, 1)
        proj_load_stage(sb, 0,        Ah, Al, Bh, Bl, m0, n0, 0,     tid);
        CP_COMMIT();
        proj_load_stage(sb, PJ_STAGE, Ah, Al, Bh, Bl, m0, n0, PJ_BK, tid);
        CP_COMMIT();

        int cur = 0;
        int nxt = 2;
        for (int kt = 0; kt < PJ_NCH; kt++) {
            CP_WAIT1();
            __syncthreads();

            if (kt + 2 < PJ_NCH) {
                proj_load_stage(sb, (uint32_t)(nxt * PJ_STAGE),
                                Ah, Al, Bh, Bl, m0, n0, (kt + 2) * PJ_BK, tid);
            }
            CP_COMMIT();   // empty group on tail iterations keeps the ledger uniform

            const uint32_t stg = sb + (uint32_t)(cur * PJ_STAGE);

#pragma unroll
            for (int ks = 0; ks < 2; ks++) {
                const int ch = ks * 2 + lkh;
                uint32_t ah[2][4], al[2][4], bh[4][4], bl[4][4];
#pragma unroll
                for (int t = 0; t < 2; t++) {
                    const int ar = warp_m * 32 + t * 16 + lrow;
                    const uint32_t aaddr = stg + (uint32_t)(ar * 64 + ((ch ^ ((ar >> 1) & 3)) * 16));
                    LDM4(ah[t], aaddr);
                    LDM4(al[t], aaddr + 8192);
                }
#pragma unroll
                for (int g = 0; g < 4; g++) {
                    const int br = warp_n * 64 + g * 16 + lrow;
                    const uint32_t baddr = stg + 16384u + (uint32_t)(br * 64 + ((ch ^ ((br >> 1) & 3)) * 16));
                    LDM4(bh[g], baddr);
                    LDM4(bl[g], baddr + 8192);
                }
#pragma unroll
                for (int t = 0; t < 2; t++)
#pragma unroll
                    for (int g = 0; g < 4; g++) {
                        mma16816(acc[t][2 * g + 0], ah[t], bh[g][0], bh[g][2]);
                        mma16816(acc[t][2 * g + 1], ah[t], bh[g][1], bh[g][3]);
                    }
#pragma unroll
                for (int t = 0; t < 2; t++)
#pragma unroll
                    for (int g = 0; g < 4; g++) {
                        mma16816(acc[t][2 * g + 0], al[t], bh[g][0], bh[g][2]);
                        mma16816(acc[t][2 * g + 1], al[t], bh[g][1], bh[g][3]);
                    }
#pragma unroll
                for (int t = 0; t < 2; t++)
#pragma unroll
                    for (int g = 0; g < 4; g++) {
                        mma16816(acc[t][2 * g + 0], ah[t], bl[g][0], bl[g][2]);
                        mma16816(acc[t][2 * g + 1], ah[t], bl[g][1], bl[g][3]);
                    }
            }

            cur = (cur == 2) ? 0 : cur + 1;
            nxt = (nxt == 2) ? 0 : nxt + 1;
        }

        // Epilogue: add bias, (Q only) fold in softmax scale, split hi/lo, store.
        const float osc = (which == 0) ? 0.18033688f : 1.0f;   // 0.125 * log2(e)
#pragma unroll
        for (int t = 0; t < 2; t++) {
#pragma unroll
            for (int j = 0; j < 8; j++) {
                const int col = warp_n * 64 + j * 8 + tpos * 2;
                const float b0 = bias[n0 + col], b1 = bias[n0 + col + 1];
                const int r0 = m0 + warp_m * 32 + t * 16 + quad;
                const size_t i0 = (size_t)r0 * DD + n0 + col;
                const size_t i1 = (size_t)(r0 + 8) * DD + n0 + col;
                uint32_t lo;
                uint32_t hp = pack_split2((acc[t][j][0] + b0) * osc,
                                          (acc[t][j][1] + b1) * osc, lo);
                *(uint32_t*)(Yh + i0) = hp;
                *(uint32_t*)(Yl + i0) = lo;
                hp = pack_split2((acc[t][j][2] + b0) * osc,
                                 (acc[t][j][3] + b1) * osc, lo);
                *(uint32_t*)(Yh + i1) = hp;
                *(uint32_t*)(Yl + i1) = lo;
            }
        }
        __syncthreads();   // all warps done with this item before slot is rewritten
    }
}

// ---------------------------------------------------------------------------
// Tensor-core flash attention: PERSISTENT grid + dynamic work queue.
// 1024 items = bh(64) x q-tile(16), bh-major so concurrent items share K/V.
// ---------------------------------------------------------------------------
#define AT_NB 64
#define AT_NCH (SS / AT_NB)        // 32
#define AT_STAGE0 32768
#define AT_STG_SZ 32768
#define AT_SMEM (AT_STAGE0 + 2 * AT_STG_SZ + 16)   // 96KB + item slot
#define AT_ITEMS 1024
#define AT_GRID 296

__device__ __forceinline__ void attn_load_kv(
    uint32_t sb, uint32_t stage_off, size_t kvbase, int kb0, int tid)
{
#pragma unroll
    for (int q = 0; q < 4; q++) {
        const int id = tid * 4 + q;            // 0..511
        const int row = id >> 3;               // 0..63
        const int ch = id & 7;
        const uint32_t so = stage_off + (uint32_t)(row * 128 + ((ch ^ (row & 7)) * 16));
        const size_t g = kvbase + (size_t)(kb0 + row) * DD + ch * 8;
        CP_ASYNC16(sb + so,          (const void*)(g_kh + g));
        CP_ASYNC16(sb + so + 8192,   (const void*)(g_kl + g));
        CP_ASYNC16(sb + so + 16384,  (const void*)(g_vh + g));
        CP_ASYNC16(sb + so + 24576,  (const void*)(g_vl + g));
    }
}

__global__ __launch_bounds__(128, 2) void attn_mma(float* __restrict__ out)
{
    extern __shared__ char smraw[];
    const uint32_t sb = smem_u32(smraw);
    const uint32_t slot = sb + AT_STAGE0 + 2 * AT_STG_SZ;

    const int tid = threadIdx.x;
    const int wid = tid >> 5;                  // 0..3
    const int lane = tid & 31;
    const int quad = lane >> 2;
    const int tpos = lane & 3;
    const int lrow = lane & 15;
    const int lhal = lane >> 4;

    for (;;) {
        if (tid == 0) {
            unsigned int it = atomicAdd(&g_ctr[1], 1u);
            asm volatile("st.shared.u32 [%0], %1;" :: "r"(slot), "r"(it));
        }
        __syncthreads();
        unsigned int item;
        asm volatile("ld.shared.u32 %0, [%1];" : "=r"(item) : "r"(slot));
        if (item >= AT_ITEMS) break;

        const int bh = (int)(item >> 4);
        const int b = bh >> 4;
        const int h = bh & 15;
        const int q0 = (int)(item & 15) * 128;

        const size_t qbase = ((size_t)(b * SS + q0)) * DD + h * HDIM;
        const size_t kvbase = ((size_t)b * SS) * DD + h * HDIM;

        // Q tile load (hi/lo), swizzled.
#pragma unroll
        for (int q = 0; q < 8; q++) {
            const int id = tid + q * 128;          // 0..1023
            const int row = id >> 3;               // 0..127
            const int ch = id & 7;
            const uint32_t so = (uint32_t)(row * 128 + ((ch ^ (row & 7)) * 16));
            const size_t g = qbase + (size_t)row * DD + ch * 8;
            CP_ASYNC16(sb + so,          (const void*)(g_qh + g));
            CP_ASYNC16(sb + 16384 + so,  (const void*)(g_ql + g));
        }
        attn_load_kv(sb, AT_STAGE0, kvbase, 0, tid);
        CP_COMMIT();                                // group: Q + KV0
        attn_load_kv(sb, AT_STAGE0 + AT_STG_SZ, kvbase, AT_NB, tid);
        CP_COMMIT();                                // group: KV1

        float oacc[2][8][4];
#pragma unroll
        for (int t = 0; t < 2; t++)
#pragma unroll
            for (int j = 0; j < 8; j++)
#pragma unroll
                for (int c = 0; c < 4; c++) oacc[t][j][c] = 0.0f;
        float mrow[4], lrun[4];
#pragma unroll
        for (int i = 0; i < 4; i++) { mrow[i] = -1e30f; lrun[i] = 0.0f; }

        for (int kt = 0; kt < AT_NCH; kt++) {
            if (kt < AT_NCH - 1) { CP_WAIT1(); } else { CP_WAIT0(); }
            __syncthreads();

            const uint32_t stg = sb + AT_STAGE0 + (uint32_t)((kt & 1) * AT_STG_SZ);

            // ---- S = Q K^T (M32 x N64 x K64 per warp), bf16x3 ----
            float sacc[2][8][4];
#pragma unroll
            for (int t = 0; t < 2; t++)
#pragma unroll
                for (int j = 0; j < 8; j++)
#pragma unroll
                    for (int c = 0; c < 4; c++) sacc[t][j][c] = 0.0f;

#pragma unroll
            for (int ks = 0; ks < 4; ks++) {
                const int ch = 2 * ks + lhal;
                uint32_t ah[2][4], al[2][4];
#pragma unroll
                for (int t = 0; t < 2; t++) {
                    const int ar = wid * 32 + t * 16 + lrow;
                    const uint32_t aaddr = sb + (uint32_t)(ar * 128 + ((ch ^ (ar & 7)) * 16));
                    LDM4(ah[t], aaddr);
                    LDM4(al[t], aaddr + 16384);
                }
#pragma unroll
                for (int gp = 0; gp < 2; gp++) {
                    uint32_t bh4[2][4], bl4[2][4];
#pragma unroll
                    for (int gg = 0; gg < 2; gg++) {
                        const int kr = (gp * 2 + gg) * 16 + lrow;
                        const uint32_t baddr = stg + (uint32_t)(kr * 128 + ((ch ^ (kr & 7)) * 16));
                        LDM4(bh4[gg], baddr);
                        LDM4(bl4[gg], baddr + 8192);
                    }
#pragma unroll
                    for (int t = 0; t < 2; t++)
#pragma unroll
                        for (int gg = 0; gg < 2; gg++) {
                            const int g = gp * 2 + gg;
                            mma16816(sacc[t][2 * g + 0], ah[t], bh4[gg][0], bh4[gg][2]);
                            mma16816(sacc[t][2 * g + 1], ah[t], bh4[gg][1], bh4[gg][3]);
                        }
#pragma unroll
                    for (int t = 0; t < 2; t++)
#pragma unroll
                        for (int gg = 0; gg < 2; gg++) {
                            const int g = gp * 2 + gg;
                            mma16816(sacc[t][2 * g + 0], al[t], bh4[gg][0], bh4[gg][2]);
                            mma16816(sacc[t][2 * g + 1], al[t], bh4[gg][1], bh4[gg][3]);
                        }
#pragma unroll
                    for (int t = 0; t < 2; t++)
#pragma unroll
                        for (int gg = 0; gg < 2; gg++) {
                            const int g = gp * 2 + gg;
                            mma16816(sacc[t][2 * g + 0], ah[t], bl4[gg][0], bl4[gg][2]);
                            mma16816(sacc[t][2 * g + 1], ah[t], bl4[gg][1], bl4[gg][3]);
                        }
                }
            }

            // ---- online softmax (log2 domain; Q pre-scaled) ----
#pragma unroll
            for (int t = 0; t < 2; t++) {
                float t0 = -1e30f, t1 = -1e30f;
#pragma unroll
                for (int j = 0; j < 8; j++) {
                    t0 = fmaxf(t0, fmaxf(sacc[t][j][0], sacc[t][j][1]));
                    t1 = fmaxf(t1, fmaxf(sacc[t][j][2], sacc[t][j][3]));
                }
                t0 = fmaxf(t0, __shfl_xor_sync(0xffffffffu, t0, 1));
                t0 = fmaxf(t0, __shfl_xor_sync(0xffffffffu, t0, 2));
                t1 = fmaxf(t1, __shfl_xor_sync(0xffffffffu, t1, 1));
                t1 = fmaxf(t1, __shfl_xor_sync(0xffffffffu, t1, 2));

                const int i0 = 2 * t, i1 = 2 * t + 1;
                const float mn0 = fmaxf(mrow[i0], t0);
                const float mn1 = fmaxf(mrow[i1], t1);
                const float corr0 = ex2(mrow[i0] - mn0);
                const float corr1 = ex2(mrow[i1] - mn1);
                mrow[i0] = mn0; mrow[i1] = mn1;

                float rs0 = 0.0f, rs1 = 0.0f;
#pragma unroll
                for (int j = 0; j < 8; j++) {
                    sacc[t][j][0] = ex2(sacc[t][j][0] - mn0);
                    sacc[t][j][1] = ex2(sacc[t][j][1] - mn0);
                    sacc[t][j][2] = ex2(sacc[t][j][2] - mn1);
                    sacc[t][j][3] = ex2(sacc[t][j][3] - mn1);
                    rs0 += sacc[t][j][0] + sacc[t][j][1];
                    rs1 += sacc[t][j][2] + sacc[t][j][3];
                }
                rs0 += __shfl_xor_sync(0xffffffffu, rs0, 1);
                rs0 += __shfl_xor_sync(0xffffffffu, rs0, 2);
                rs1 += __shfl_xor_sync(0xffffffffu, rs1, 1);
                rs1 += __shfl_xor_sync(0xffffffffu, rs1, 2);
                lrun[i0] = lrun[i0] * corr0 + rs0;
                lrun[i1] = lrun[i1] * corr1 + rs1;

#pragma unroll
                for (int j = 0; j < 8; j++) {
                    oacc[t][j][0] *= corr0; oacc[t][j][1] *= corr0;
                    oacc[t][j][2] *= corr1; oacc[t][j][3] *= corr1;
                }
            }

            // ---- O += P V (M32 x N64 x K64 per warp), bf16x3 ----
#pragma unroll
            for (int ks = 0; ks < 4; ks++) {
                uint32_t ph[2][4], pl[2][4];
#pragma unroll
                for (int t = 0; t < 2; t++) {
                    ph[t][0] = pack_split2(sacc[t][2 * ks][0],     sacc[t][2 * ks][1],     pl[t][0]);
                    ph[t][1] = pack_split2(sacc[t][2 * ks][2],     sacc[t][2 * ks][3],     pl[t][1]);
                    ph[t][2] = pack_split2(sacc[t][2 * ks + 1][0], sacc[t][2 * ks + 1][1], pl[t][2]);
                    ph[t][3] = pack_split2(sacc[t][2 * ks + 1][2], sacc[t][2 * ks + 1][3], pl[t][3]);
                }
#pragma unroll
                for (int gp = 0; gp < 2; gp++) {
                    uint32_t vh4[2][4], vl4[2][4];
#pragma unroll
                    for (int gg = 0; gg < 2; gg++) {
                        const int vk = ks * 16 + lrow;
                        const int cn = 2 * (gp * 2 + gg) + lhal;
                        const uint32_t vaddr = stg + 16384u +
                            (uint32_t)(vk * 128 + ((cn ^ (vk & 7)) * 16));
                        LDM4T(vh4[gg], vaddr);
                        LDM4T(vl4[gg], vaddr + 8192);
                    }
#pragma unroll
                    for (int t = 0; t < 2; t++)
#pragma unroll
                        for (int gg = 0; gg < 2; gg++) {
                            const int g = gp * 2 + gg;
                            mma16816(oacc[t][2 * g + 0], ph[t], vh4[gg][0], vh4[gg][1]);
                            mma16816(oacc[t][2 * g + 1], ph[t], vh4[gg][2], vh4[gg][3]);
                        }
#pragma unroll
                    for (int t = 0; t < 2; t++)
#pragma unroll
                        for (int gg = 0; gg < 2; gg++) {
                            const int g = gp * 2 + gg;
                            mma16816(oacc[t][2 * g + 0], pl[t], vh4[gg][0], vh4[gg][1]);
                            mma16816(oacc[t][2 * g + 1], pl[t], vh4[gg][2], vh4[gg][3]);
                        }
#pragma unroll
                    for (int t = 0; t < 2; t++)
#pragma unroll
                        for (int gg = 0; gg < 2; gg++) {
                            const int g = gp * 2 + gg;
                            mma16816(oacc[t][2 * g + 0], ph[t], vl4[gg][0], vl4[gg][1]);
                            mma16816(oacc[t][2 * g + 1], ph[t], vl4[gg][2], vl4[gg][3]);
                        }
                }
            }

            __syncthreads();
            if (kt + 2 < AT_NCH) {
                attn_load_kv(sb, AT_STAGE0 + (uint32_t)((kt & 1) * AT_STG_SZ),
                             kvbase, (kt + 2) * AT_NB, tid);
                CP_COMMIT();
            }
        }

        // Epilogue: normalize, write [B,S,D]
#pragma unroll
        for (int t = 0; t < 2; t++) {
            const float inv0 = 1.0f / lrun[2 * t];
            const float inv1 = 1.0f / lrun[2 * t + 1];
            const int rowA = q0 + wid * 32 + t * 16 + quad;
#pragma unroll
            for (int j = 0; j < 8; j++) {
                const int col = h * HDIM + j * 8 + tpos * 2;
                *(float2*)(out + ((size_t)(b * SS + rowA)) * DD + col) =
                    make_float2(oacc[t][j][0] * inv0, oacc[t][j][1] * inv0);
                *(float2*)(out + ((size_t)(b * SS + rowA + 8)) * DD + col) =
                    make_float2(oacc[t][j][2] * inv1, oacc[t][j][3] * inv1);
            }
        }
        __syncthreads();   // all warps done with this item before slot is rewritten
    }
}

// ---------------------------------------------------------------------------
extern "C" void kernel_launch(void* const* d_in, const int* in_sizes, int n_in,
                              void* d_out, int out_size)
{
    (void)in_sizes; (void)n_in; (void)out_size;
    const float* query = (const float*)d_in[0];
    const float* key   = (const float*)d_in[1];
    const float* value = (const float*)d_in[2];
    const float* Wq    = (const float*)d_in[3];
    const float* bq    = (const float*)d_in[4];
    const float* Wk    = (const float*)d_in[5];
    const float* bk    = (const float*)d_in[6];
    const float* Wv    = (const float*)d_in[7];
    const float* bv    = (const float*)d_in[8];

    cudaFuncSetAttribute(proj_mma, cudaFuncAttributeMaxDynamicSharedMemorySize, PJ_SMEM);
    cudaFuncSetAttribute(attn_mma, cudaFuncAttributeMaxDynamicSharedMemorySize, AT_SMEM);

    reset_ctrs<<<1, 1>>>();
    convert_x<<<dim3(MTOT * DD / 1024, 1, 3), 256>>>(query, key, value);
    convert_w<<<dim3(DD * DD / 1024, 1, 3), 256>>>(Wq, Wk, Wv);

    proj_mma<<<PJ_GRID, 256, PJ_SMEM>>>(bq, bk, bv);

    attn_mma<<<AT_GRID, 128, AT_SMEM>>>((float*)d_out);
}

// round 13
// speedup vs baseline: 1.0403x; 1.0403x over previous
#include <cuda_runtime.h>
#include <cuda_bf16.h>
#include <cstdint>

#define BB 4
#define SS 2048
#define DD 1024
#define HH 16
#define HDIM 64
#define MTOT (BB * SS)   // 8192

// ---------------------------------------------------------------------------
// Device scratch (static globals: no runtime allocation)
// ---------------------------------------------------------------------------
__device__ __nv_bfloat16 g_xhi[(size_t)3 * MTOT * DD];
__device__ __nv_bfloat16 g_xlo[(size_t)3 * MTOT * DD];
__device__ __nv_bfloat16 g_whi[(size_t)3 * DD * DD];
__device__ __nv_bfloat16 g_wlo[(size_t)3 * DD * DD];

__device__ __nv_bfloat16 g_qh[(size_t)MTOT * DD];
__device__ __nv_bfloat16 g_ql[(size_t)MTOT * DD];
__device__ __nv_bfloat16 g_kh[(size_t)MTOT * DD];
__device__ __nv_bfloat16 g_kl[(size_t)MTOT * DD];
__device__ __nv_bfloat16 g_vh[(size_t)MTOT * DD];
__device__ __nv_bfloat16 g_vl[(size_t)MTOT * DD];

// ---------------------------------------------------------------------------
// Helpers
// ---------------------------------------------------------------------------
__device__ __forceinline__ uint32_t smem_u32(const void* p) {
    uint32_t a;
    asm("{ .reg .u64 t; cvta.to.shared.u64 t, %1; cvt.u32.u64 %0, t; }"
        : "=r"(a) : "l"(p));
    return a;
}

__device__ __forceinline__ void bf16_split(float x, uint32_t& h, uint32_t& l) {
    __nv_bfloat16 hb = __float2bfloat16(x);
    __nv_bfloat16 lb = __float2bfloat16(x - __bfloat162float(hb));
    h = (uint32_t)__bfloat16_as_ushort(hb);
    l = (uint32_t)__bfloat16_as_ushort(lb);
}

// Pack (f0 -> low half, f1 -> high half) into bf16x2; also produce the residual pair.
__device__ __forceinline__ uint32_t pack_split2(float f0, float f1, uint32_t& lo) {
    uint32_t hp;
    asm("cvt.rn.bf16x2.f32 %0, %1, %2;" : "=r"(hp) : "f"(f1), "f"(f0));
    float h0 = __bfloat162float(__ushort_as_bfloat16((unsigned short)(hp & 0xffffu)));
    float h1 = __bfloat162float(__ushort_as_bfloat16((unsigned short)(hp >> 16)));
    asm("cvt.rn.bf16x2.f32 %0, %1, %2;" : "=r"(lo) : "f"(f1 - h1), "f"(f0 - h0));
    return hp;
}

__device__ __forceinline__ float ex2(float x) {
    float r;
    asm("ex2.approx.f32 %0, %1;" : "=f"(r) : "f"(x));
    return r;
}

__device__ __forceinline__ void mma16816(float* c, const uint32_t* a,
                                         uint32_t b0, uint32_t b1) {
    asm volatile(
        "mma.sync.aligned.m16n8k16.row.col.f32.bf16.bf16.f32 "
        "{%0,%1,%2,%3}, {%4,%5,%6,%7}, {%8,%9}, {%0,%1,%2,%3};"
        : "+f"(c[0]), "+f"(c[1]), "+f"(c[2]), "+f"(c[3])
        : "r"(a[0]), "r"(a[1]), "r"(a[2]), "r"(a[3]), "r"(b0), "r"(b1));
}

#define LDM4(r, addr)                                                         \
    asm volatile("ldmatrix.sync.aligned.m8n8.x4.shared.b16 {%0,%1,%2,%3}, [%4];" \
                 : "=r"((r)[0]), "=r"((r)[1]), "=r"((r)[2]), "=r"((r)[3])     \
                 : "r"(addr))

#define LDM4T(r, addr)                                                        \
    asm volatile("ldmatrix.sync.aligned.m8n8.x4.trans.shared.b16 {%0,%1,%2,%3}, [%4];" \
                 : "=r"((r)[0]), "=r"((r)[1]), "=r"((r)[2]), "=r"((r)[3])     \
                 : "r"(addr))

#define CP_ASYNC16(saddr, gaddr)                                              \
    asm volatile("cp.async.cg.shared.global [%0], [%1], 16;"                  \
                 :: "r"(saddr), "l"(gaddr))
#define CP_COMMIT() asm volatile("cp.async.commit_group;")
#define CP_WAIT1()  asm volatile("cp.async.wait_group 1;")
#define CP_WAIT0()  asm volatile("cp.async.wait_group 0;")

// ---------------------------------------------------------------------------
// Input converts: fp32 -> bf16 hi/lo
// ---------------------------------------------------------------------------
__global__ __launch_bounds__(256) void convert_x(
    const float* __restrict__ xq, const float* __restrict__ xk, const float* __restrict__ xv)
{
    const float* src = (blockIdx.z == 0) ? xq : (blockIdx.z == 1) ? xk : xv;
    size_t i = ((size_t)blockIdx.x * 256 + threadIdx.x) * 4;
    size_t o = (size_t)blockIdx.z * MTOT * DD + i;
    float4 x = *(const float4*)(src + i);
    uint32_t h0, l0, h1, l1, h2, l2, h3, l3;
    bf16_split(x.x, h0, l0); bf16_split(x.y, h1, l1);
    bf16_split(x.z, h2, l2); bf16_split(x.w, h3, l3);
    uint2 hv, lv;
    hv.x = h0 | (h1 << 16); hv.y = h2 | (h3 << 16);
    lv.x = l0 | (l1 << 16); lv.y = l2 | (l3 << 16);
    *(uint2*)(g_xhi + o) = hv;
    *(uint2*)(g_xlo + o) = lv;
}

__global__ __launch_bounds__(256) void convert_w(
    const float* __restrict__ wq, const float* __restrict__ wk, const float* __restrict__ wv)
{
    const float* src = (blockIdx.z == 0) ? wq : (blockIdx.z == 1) ? wk : wv;
    size_t i = ((size_t)blockIdx.x * 256 + threadIdx.x) * 4;
    size_t o = (size_t)blockIdx.z * DD * DD + i;
    float4 x = *(const float4*)(src + i);
    uint32_t h0, l0, h1, l1, h2, l2, h3, l3;
    bf16_split(x.x, h0, l0); bf16_split(x.y, h1, l1);
    bf16_split(x.z, h2, l2); bf16_split(x.w, h3, l3);
    uint2 hv, lv;
    hv.x = h0 | (h1 << 16); hv.y = h2 | (h3 << 16);
    lv.x = l0 | (l1 << 16); lv.y = l2 | (l3 << 16);
    *(uint2*)(g_whi + o) = hv;
    *(uint2*)(g_wlo + o) = lv;
}

// ---------------------------------------------------------------------------
// bf16x3 projection GEMM via mma.sync (R7-verified structure).
// CTA tile 128x128, BK=32, 8 warps as 4(M) x 2(N), warp tile 32x64.
// cp.async 2-stage double buffer; Q output pre-scaled by 0.125*log2(e).
// ---------------------------------------------------------------------------
#define PJ_BK 32
#define PJ_NCH (DD / PJ_BK)     // 32
#define PJ_STAGE 32768
#define PJ_SMEM (2 * PJ_STAGE)  // 64KB

__device__ __forceinline__ void proj_load_stage(
    uint32_t sb, uint32_t stage_off,
    const __nv_bfloat16* __restrict__ Ah, const __nv_bfloat16* __restrict__ Al,
    const __nv_bfloat16* __restrict__ Bh, const __nv_bfloat16* __restrict__ Bl,
    int m0, int n0, int k0, int tid)
{
#pragma unroll
    for (int q = 0; q < 2; q++) {
        const int id = tid * 2 + q;
        const int row = id >> 2;
        const int ch = id & 3;
        const uint32_t so = stage_off + (uint32_t)(row * 64 + ((ch ^ ((row >> 1) & 3)) * 16));
        const size_t ga = (size_t)(m0 + row) * DD + k0 + ch * 8;
        const size_t gb = (size_t)(n0 + row) * DD + k0 + ch * 8;
        CP_ASYNC16(sb + so,          (const void*)(Ah + ga));
        CP_ASYNC16(sb + so + 8192,   (const void*)(Al + ga));
        CP_ASYNC16(sb + so + 16384,  (const void*)(Bh + gb));
        CP_ASYNC16(sb + so + 24576,  (const void*)(Bl + gb));
    }
}

__global__ __launch_bounds__(256, 2) void proj_mma(
    const float* __restrict__ bq, const float* __restrict__ bk, const float* __restrict__ bv)
{
    extern __shared__ char smraw[];
    const uint32_t sb = smem_u32(smraw);

    const int tid = threadIdx.x;
    const int wid = tid >> 5;
    const int lane = tid & 31;
    const int warp_m = wid & 3;
    const int warp_n = wid >> 2;
    const int which = blockIdx.z;
    const int n0 = blockIdx.x * 128;
    const int m0 = blockIdx.y * 128;

    const __nv_bfloat16* Ah = g_xhi + (size_t)which * MTOT * DD;
    const __nv_bfloat16* Al = g_xlo + (size_t)which * MTOT * DD;
    const __nv_bfloat16* Bh = g_whi + (size_t)which * DD * DD;
    const __nv_bfloat16* Bl = g_wlo + (size_t)which * DD * DD;
    const float* bias = (which == 0) ? bq : (which == 1) ? bk : bv;
    __nv_bfloat16* Yh = (which == 0) ? g_qh : (which == 1) ? g_kh : g_vh;
    __nv_bfloat16* Yl = (which == 0) ? g_ql : (which == 1) ? g_kl : g_vl;

    float acc[2][8][4];
#pragma unroll
    for (int t = 0; t < 2; t++)
#pragma unroll
        for (int j = 0; j < 8; j++)
#pragma unroll
            for (int c = 0; c < 4; c++) acc[t][j][c] = 0.0f;

    proj_load_stage(sb, 0,        Ah, Al, Bh, Bl, m0, n0, 0,     tid);
    CP_COMMIT();
    proj_load_stage(sb, PJ_STAGE, Ah, Al, Bh, Bl, m0, n0, PJ_BK, tid);
    CP_COMMIT();

    const int lrow = lane & 15;
    const int lkh = lane >> 4;

    for (int kt = 0; kt < PJ_NCH; kt++) {
        if (kt < PJ_NCH - 1) { CP_WAIT1(); } else { CP_WAIT0(); }
        __syncthreads();

        const uint32_t stg = sb + (uint32_t)((kt & 1) * PJ_STAGE);

#pragma unroll
        for (int ks = 0; ks < 2; ks++) {
            const int ch = ks * 2 + lkh;
            uint32_t ah[2][4], al[2][4], bh[4][4], bl[4][4];
#pragma unroll
            for (int t = 0; t < 2; t++) {
                const int ar = warp_m * 32 + t * 16 + lrow;
                const uint32_t aaddr = stg + (uint32_t)(ar * 64 + ((ch ^ ((ar >> 1) & 3)) * 16));
                LDM4(ah[t], aaddr);
                LDM4(al[t], aaddr + 8192);
            }
#pragma unroll
            for (int g = 0; g < 4; g++) {
                const int br = warp_n * 64 + g * 16 + lrow;
                const uint32_t baddr = stg + 16384u + (uint32_t)(br * 64 + ((ch ^ ((br >> 1) & 3)) * 16));
                LDM4(bh[g], baddr);
                LDM4(bl[g], baddr + 8192);
            }
#pragma unroll
            for (int t = 0; t < 2; t++)
#pragma unroll
                for (int g = 0; g < 4; g++) {
                    mma16816(acc[t][2 * g + 0], ah[t], bh[g][0], bh[g][2]);
                    mma16816(acc[t][2 * g + 1], ah[t], bh[g][1], bh[g][3]);
                    mma16816(acc[t][2 * g + 0], al[t], bh[g][0], bh[g][2]);
                    mma16816(acc[t][2 * g + 1], al[t], bh[g][1], bh[g][3]);
                    mma16816(acc[t][2 * g + 0], ah[t], bl[g][0], bl[g][2]);
                    mma16816(acc[t][2 * g + 1], ah[t], bl[g][1], bl[g][3]);
                }
        }

        __syncthreads();
        if (kt + 2 < PJ_NCH) {
            proj_load_stage(sb, (uint32_t)((kt & 1) * PJ_STAGE),
                            Ah, Al, Bh, Bl, m0, n0, (kt + 2) * PJ_BK, tid);
            CP_COMMIT();
        }
    }

    // Epilogue: add bias, (Q only) fold in softmax scale, split hi/lo, store.
    const float osc = (which == 0) ? 0.18033688f : 1.0f;   // 0.125 * log2(e)
    const int quad = lane >> 2;
    const int tpos = lane & 3;
#pragma unroll
    for (int t = 0; t < 2; t++) {
#pragma unroll
        for (int j = 0; j < 8; j++) {
            const int col = warp_n * 64 + j * 8 + tpos * 2;
            const float b0 = bias[n0 + col], b1 = bias[n0 + col + 1];
            const int r0 = m0 + warp_m * 32 + t * 16 + quad;
            const size_t i0 = (size_t)r0 * DD + n0 + col;
            const size_t i1 = (size_t)(r0 + 8) * DD + n0 + col;
            uint32_t lo;
            uint32_t hp = pack_split2((acc[t][j][0] + b0) * osc,
                                      (acc[t][j][1] + b1) * osc, lo);
            *(uint32_t*)(Yh + i0) = hp;
            *(uint32_t*)(Yl + i0) = lo;
            hp = pack_split2((acc[t][j][2] + b0) * osc,
                             (acc[t][j][3] + b1) * osc, lo);
            *(uint32_t*)(Yh + i1) = hp;
            *(uint32_t*)(Yl + i1) = lo;
        }
    }
}

// ---------------------------------------------------------------------------
// Tensor-core flash attention, bf16x3 both GEMMs (R7-verified structure).
// CTA: 128 queries x one (b,h); 32 key-blocks of 64. 8 warps, warp = 16 rows.
// Q arrives pre-scaled by 0.125*log2(e) (folded into the projection).
// smem: Q hi/lo 32KB + 2 stages x (Khi,Klo,Vhi,Vlo 8KB each) = 96KB.
// ---------------------------------------------------------------------------
#define AT_NB 64
#define AT_NCH (SS / AT_NB)        // 32
#define AT_STAGE0 32768
#define AT_STG_SZ 32768
#define AT_SMEM (AT_STAGE0 + 2 * AT_STG_SZ)   // 98304

__device__ __forceinline__ void attn_load_kv(
    uint32_t sb, uint32_t stage_off, size_t kvbase, int kb0, int tid)
{
#pragma unroll
    for (int q = 0; q < 2; q++) {
        const int id = tid * 2 + q;            // 0..511
        const int row = id >> 3;               // 0..63
        const int ch = id & 7;
        const uint32_t so = stage_off + (uint32_t)(row * 128 + ((ch ^ (row & 7)) * 16));
        const size_t g = kvbase + (size_t)(kb0 + row) * DD + ch * 8;
        CP_ASYNC16(sb + so,          (const void*)(g_kh + g));
        CP_ASYNC16(sb + so + 8192,   (const void*)(g_kl + g));
        CP_ASYNC16(sb + so + 16384,  (const void*)(g_vh + g));
        CP_ASYNC16(sb + so + 24576,  (const void*)(g_vl + g));
    }
}

__global__ __launch_bounds__(256, 2) void attn_mma(float* __restrict__ out)
{
    extern __shared__ char smraw[];
    const uint32_t sb = smem_u32(smraw);

    const int tid = threadIdx.x;
    const int wid = tid >> 5;
    const int lane = tid & 31;
    const int quad = lane >> 2;
    const int tpos = lane & 3;
    const int lrow = lane & 15;
    const int lhal = lane >> 4;

    const int bh = blockIdx.y;
    const int b = bh >> 4;
    const int h = bh & 15;
    const int q0 = blockIdx.x * 128;

    const size_t qbase = ((size_t)(b * SS + q0)) * DD + h * HDIM;
    const size_t kvbase = ((size_t)b * SS) * DD + h * HDIM;

    // Q tile load (hi/lo), swizzled.
#pragma unroll
    for (int q = 0; q < 4; q++) {
        const int id = tid + q * 256;          // 0..1023
        const int row = id >> 3;               // 0..127
        const int ch = id & 7;
        const uint32_t so = (uint32_t)(row * 128 + ((ch ^ (row & 7)) * 16));
        const size_t g = qbase + (size_t)row * DD + ch * 8;
        CP_ASYNC16(sb + so,          (const void*)(g_qh + g));
        CP_ASYNC16(sb + 16384 + so,  (const void*)(g_ql + g));
    }
    attn_load_kv(sb, AT_STAGE0, kvbase, 0, tid);
    CP_COMMIT();                                // group 0: Q + KV0
    attn_load_kv(sb, AT_STAGE0 + AT_STG_SZ, kvbase, AT_NB, tid);
    CP_COMMIT();                                // group 1: KV1

    float oacc[8][4];
#pragma unroll
    for (int j = 0; j < 8; j++)
#pragma unroll
        for (int c = 0; c < 4; c++) oacc[j][c] = 0.0f;
    float mrow0 = -1e30f, mrow1 = -1e30f, lrow0 = 0.0f, lrow1 = 0.0f;

    for (int kt = 0; kt < AT_NCH; kt++) {
        if (kt < AT_NCH - 1) { CP_WAIT1(); } else { CP_WAIT0(); }
        __syncthreads();

        const uint32_t stg = sb + AT_STAGE0 + (uint32_t)((kt & 1) * AT_STG_SZ);

        // ---- S = Q K^T (M16 x N64 x K64 per warp), bf16x3 ----
        float sacc[8][4];
#pragma unroll
        for (int j = 0; j < 8; j++)
#pragma unroll
            for (int c = 0; c < 4; c++) sacc[j][c] = 0.0f;

#pragma unroll
        for (int ks = 0; ks < 4; ks++) {
            const int ch = 2 * ks + lhal;
            uint32_t ah[4], al[4];
            {
                const int ar = wid * 16 + lrow;
                const uint32_t aaddr = sb + (uint32_t)(ar * 128 + ((ch ^ (ar & 7)) * 16));
                LDM4(ah, aaddr);
                LDM4(al, aaddr + 16384);
            }
#pragma unroll
            for (int g = 0; g < 4; g++) {
                const int kr = g * 16 + lrow;
                const uint32_t baddr = stg + (uint32_t)(kr * 128 + ((ch ^ (kr & 7)) * 16));
                uint32_t bh4[4], bl4[4];
                LDM4(bh4, baddr);
                LDM4(bl4, baddr + 8192);
                mma16816(sacc[2 * g + 0], ah, bh4[0], bh4[2]);
                mma16816(sacc[2 * g + 1], ah, bh4[1], bh4[3]);
                mma16816(sacc[2 * g + 0], al, bh4[0], bh4[2]);
                mma16816(sacc[2 * g + 1], al, bh4[1], bh4[3]);
                mma16816(sacc[2 * g + 0], ah, bl4[0], bl4[2]);
                mma16816(sacc[2 * g + 1], ah, bl4[1], bl4[3]);
            }
        }

        // ---- online softmax (log2 domain; Q pre-scaled, rows quad / quad+8) ----
        float t0 = -1e30f, t1 = -1e30f;
#pragma unroll
        for (int j = 0; j < 8; j++) {
            t0 = fmaxf(t0, fmaxf(sacc[j][0], sacc[j][1]));
            t1 = fmaxf(t1, fmaxf(sacc[j][2], sacc[j][3]));
        }
        t0 = fmaxf(t0, __shfl_xor_sync(0xffffffffu, t0, 1));
        t0 = fmaxf(t0, __shfl_xor_sync(0xffffffffu, t0, 2));
        t1 = fmaxf(t1, __shfl_xor_sync(0xffffffffu, t1, 1));
        t1 = fmaxf(t1, __shfl_xor_sync(0xffffffffu, t1, 2));

        const float mn0 = fmaxf(mrow0, t0);
        const float mn1 = fmaxf(mrow1, t1);
        const float corr0 = ex2(mrow0 - mn0);
        const float corr1 = ex2(mrow1 - mn1);
        mrow0 = mn0; mrow1 = mn1;

        float rs0 = 0.0f, rs1 = 0.0f;
#pragma unroll
        for (int j = 0; j < 8; j++) {
            sacc[j][0] = ex2(sacc[j][0] - mn0);
            sacc[j][1] = ex2(sacc[j][1] - mn0);
            sacc[j][2] = ex2(sacc[j][2] - mn1);
            sacc[j][3] = ex2(sacc[j][3] - mn1);
            rs0 += sacc[j][0] + sacc[j][1];
            rs1 += sacc[j][2] + sacc[j][3];
        }
        rs0 += __shfl_xor_sync(0xffffffffu, rs0, 1);
        rs0 += __shfl_xor_sync(0xffffffffu, rs0, 2);
        rs1 += __shfl_xor_sync(0xffffffffu, rs1, 1);
        rs1 += __shfl_xor_sync(0xffffffffu, rs1, 2);
        lrow0 = lrow0 * corr0 + rs0;
        lrow1 = lrow1 * corr1 + rs1;

#pragma unroll
        for (int j = 0; j < 8; j++) {
            oacc[j][0] *= corr0; oacc[j][1] *= corr0;
            oacc[j][2] *= corr1; oacc[j][3] *= corr1;
        }

        // ---- O += P V (M16 x N64 x K64 per warp), bf16x3, P from registers ----
#pragma unroll
        for (int ks = 0; ks < 4; ks++) {
            uint32_t ph[4], pl[4];
            ph[0] = pack_split2(sacc[2 * ks][0],     sacc[2 * ks][1],     pl[0]);
            ph[1] = pack_split2(sacc[2 * ks][2],     sacc[2 * ks][3],     pl[1]);
            ph[2] = pack_split2(sacc[2 * ks + 1][0], sacc[2 * ks + 1][1], pl[2]);
            ph[3] = pack_split2(sacc[2 * ks + 1][2], sacc[2 * ks + 1][3], pl[3]);
#pragma unroll
            for (int g = 0; g < 4; g++) {
                const int vk = ks * 16 + lrow;
                const int cn = 2 * g + lhal;
                const uint32_t vaddr = stg + 16384u +
                    (uint32_t)(vk * 128 + ((cn ^ (vk & 7)) * 16));
                uint32_t vh4[4], vl4[4];
                LDM4T(vh4, vaddr);
                LDM4T(vl4, vaddr + 8192);
                mma16816(oacc[2 * g + 0], ph, vh4[0], vh4[1]);
                mma16816(oacc[2 * g + 1], ph, vh4[2], vh4[3]);
                mma16816(oacc[2 * g + 0], pl, vh4[0], vh4[1]);
                mma16816(oacc[2 * g + 1], pl, vh4[2], vh4[3]);
                mma16816(oacc[2 * g + 0], ph, vl4[0], vl4[1]);
                mma16816(oacc[2 * g + 1], ph, vl4[2], vl4[3]);
            }
        }

        __syncthreads();
        if (kt + 2 < AT_NCH) {
            attn_load_kv(sb, AT_STAGE0 + (uint32_t)((kt & 1) * AT_STG_SZ),
                         kvbase, (kt + 2) * AT_NB, tid);
            CP_COMMIT();
        }
    }

    // Epilogue: normalize, write [B,S,D]
    const float inv0 = 1.0f / lrow0;
    const float inv1 = 1.0f / lrow1;
    const int rowA = q0 + wid * 16 + quad;
#pragma unroll
    for (int j = 0; j < 8; j++) {
        const int col = h * HDIM + j * 8 + tpos * 2;
        *(float2*)(out + ((size_t)(b * SS + rowA)) * DD + col) =
            make_float2(oacc[j][0] * inv0, oacc[j][1] * inv0);
        *(float2*)(out + ((size_t)(b * SS + rowA + 8)) * DD + col) =
            make_float2(oacc[j][2] * inv1, oacc[j][3] * inv1);
    }
}

// ---------------------------------------------------------------------------
extern "C" void kernel_launch(void* const* d_in, const int* in_sizes, int n_in,
                              void* d_out, int out_size)
{
    (void)in_sizes; (void)n_in; (void)out_size;
    const float* query = (const float*)d_in[0];
    const float* key   = (const float*)d_in[1];
    const float* value = (const float*)d_in[2];
    const float* Wq    = (const float*)d_in[3];
    const float* bq    = (const float*)d_in[4];
    const float* Wk    = (const float*)d_in[5];
    const float* bk    = (const float*)d_in[6];
    const float* Wv    = (const float*)d_in[7];
    const float* bv    = (const float*)d_in[8];

    cudaFuncSetAttribute(proj_mma, cudaFuncAttributeMaxDynamicSharedMemorySize, PJ_SMEM);
    cudaFuncSetAttribute(attn_mma, cudaFuncAttributeMaxDynamicSharedMemorySize, AT_SMEM);

    convert_x<<<dim3(MTOT * DD / 1024, 1, 3), 256>>>(query, key, value);
    convert_w<<<dim3(DD * DD / 1024, 1, 3), 256>>>(Wq, Wk, Wv);

    proj_mma<<<dim3(DD / 128, MTOT / 128, 3), 256, PJ_SMEM>>>(bq, bk, bv);

    attn_mma<<<dim3(SS / 128, BB * HH), 256, AT_SMEM>>>((float*)d_out);
}

// round 15
// speedup vs baseline: 1.0432x; 1.0027x over previous
#include <cuda_runtime.h>
#include <cuda_bf16.h>
#include <cstdint>

#define BB 4
#define SS 2048
#define DD 1024
#define HH 16
#define HDIM 64
#define MTOT (BB * SS)   // 8192

// ---------------------------------------------------------------------------
// Device scratch (static globals: no runtime allocation)
// ---------------------------------------------------------------------------
__device__ __nv_bfloat16 g_xhi[(size_t)3 * MTOT * DD];
__device__ __nv_bfloat16 g_xlo[(size_t)3 * MTOT * DD];
__device__ __nv_bfloat16 g_whi[(size_t)3 * DD * DD];
__device__ __nv_bfloat16 g_wlo[(size_t)3 * DD * DD];

__device__ __nv_bfloat16 g_qh[(size_t)MTOT * DD];
__device__ __nv_bfloat16 g_ql[(size_t)MTOT * DD];
__device__ __nv_bfloat16 g_kh[(size_t)MTOT * DD];
__device__ __nv_bfloat16 g_kl[(size_t)MTOT * DD];
__device__ __nv_bfloat16 g_vh[(size_t)MTOT * DD];
__device__ __nv_bfloat16 g_vl[(size_t)MTOT * DD];

// ---------------------------------------------------------------------------
// Helpers
// ---------------------------------------------------------------------------
__device__ __forceinline__ uint32_t smem_u32(const void* p) {
    uint32_t a;
    asm("{ .reg .u64 t; cvta.to.shared.u64 t, %1; cvt.u32.u64 %0, t; }"
        : "=r"(a) : "l"(p));
    return a;
}

__device__ __forceinline__ void bf16_split(float x, uint32_t& h, uint32_t& l) {
    __nv_bfloat16 hb = __float2bfloat16(x);
    __nv_bfloat16 lb = __float2bfloat16(x - __bfloat162float(hb));
    h = (uint32_t)__bfloat16_as_ushort(hb);
    l = (uint32_t)__bfloat16_as_ushort(lb);
}

// Pack (f0 -> low half, f1 -> high half) into bf16x2; also produce the residual pair.
__device__ __forceinline__ uint32_t pack_split2(float f0, float f1, uint32_t& lo) {
    uint32_t hp;
    asm("cvt.rn.bf16x2.f32 %0, %1, %2;" : "=r"(hp) : "f"(f1), "f"(f0));
    float h0 = __bfloat162float(__ushort_as_bfloat16((unsigned short)(hp & 0xffffu)));
    float h1 = __bfloat162float(__ushort_as_bfloat16((unsigned short)(hp >> 16)));
    asm("cvt.rn.bf16x2.f32 %0, %1, %2;" : "=r"(lo) : "f"(f1 - h1), "f"(f0 - h0));
    return hp;
}

__device__ __forceinline__ float ex2(float x) {
    float r;
    asm("ex2.approx.f32 %0, %1;" : "=f"(r) : "f"(x));
    return r;
}

__device__ __forceinline__ void mma16816(float* c, const uint32_t* a,
                                         uint32_t b0, uint32_t b1) {
    asm volatile(
        "mma.sync.aligned.m16n8k16.row.col.f32.bf16.bf16.f32 "
        "{%0,%1,%2,%3}, {%4,%5,%6,%7}, {%8,%9}, {%0,%1,%2,%3};"
        : "+f"(c[0]), "+f"(c[1]), "+f"(c[2]), "+f"(c[3])
        : "r"(a[0]), "r"(a[1]), "r"(a[2]), "r"(a[3]), "r"(b0), "r"(b1));
}

#define LDM4(r, addr)                                                         \
    asm volatile("ldmatrix.sync.aligned.m8n8.x4.shared.b16 {%0,%1,%2,%3}, [%4];" \
                 : "=r"((r)[0]), "=r"((r)[1]), "=r"((r)[2]), "=r"((r)[3])     \
                 : "r"(addr))

#define LDM4T(r, addr)                                                        \
    asm volatile("ldmatrix.sync.aligned.m8n8.x4.trans.shared.b16 {%0,%1,%2,%3}, [%4];" \
                 : "=r"((r)[0]), "=r"((r)[1]), "=r"((r)[2]), "=r"((r)[3])     \
                 : "r"(addr))

#define CP_ASYNC16(saddr, gaddr)                                              \
    asm volatile("cp.async.cg.shared.global [%0], [%1], 16;"                  \
                 :: "r"(saddr), "l"(gaddr))
#define CP_COMMIT() asm volatile("cp.async.commit_group;")
#define CP_WAIT1()  asm volatile("cp.async.wait_group 1;")
#define CP_WAIT0()  asm volatile("cp.async.wait_group 0;")

// ---------------------------------------------------------------------------
// Input convert (merged X + W): fp32 -> bf16 hi/lo.
// grid.x: blocks 0..8191 handle X rows (1024 elems each), 8192..9215 handle W.
// grid.z selects q/k/v.
// ---------------------------------------------------------------------------
#define CVT_XBLK (MTOT * DD / 1024)   // 8192
#define CVT_WBLK (DD * DD / 1024)     // 1024

__global__ __launch_bounds__(256) void convert_all(
    const float* __restrict__ xq, const float* __restrict__ xk, const float* __restrict__ xv,
    const float* __restrict__ wq, const float* __restrict__ wk, const float* __restrict__ wv)
{
    const int z = blockIdx.z;
    const float* src;
    __nv_bfloat16* dh;
    __nv_bfloat16* dl;
    size_t base;
    if (blockIdx.x < CVT_XBLK) {
        src = (z == 0) ? xq : (z == 1) ? xk : xv;
        dh = g_xhi; dl = g_xlo;
        base = (size_t)z * MTOT * DD + (size_t)blockIdx.x * 1024;
        src += (size_t)blockIdx.x * 1024;
    } else {
        src = (z == 0) ? wq : (z == 1) ? wk : wv;
        dh = g_whi; dl = g_wlo;
        const size_t wo = (size_t)(blockIdx.x - CVT_XBLK) * 1024;
        base = (size_t)z * DD * DD + wo;
        src += wo;
    }
    const size_t i = (size_t)threadIdx.x * 4;
    float4 x = *(const float4*)(src + i);
    uint32_t h0, l0, h1, l1, h2, l2, h3, l3;
    bf16_split(x.x, h0, l0); bf16_split(x.y, h1, l1);
    bf16_split(x.z, h2, l2); bf16_split(x.w, h3, l3);
    uint2 hv, lv;
    hv.x = h0 | (h1 << 16); hv.y = h2 | (h3 << 16);
    lv.x = l0 | (l1 << 16); lv.y = l2 | (l3 << 16);
    *(uint2*)(dh + base + i) = hv;
    *(uint2*)(dl + base + i) = lv;
}

// ---------------------------------------------------------------------------
// bf16x3 projection GEMM via mma.sync (R7/R13-verified structure).
// CTA tile 128x128, BK=32, 8 warps as 4(M) x 2(N), warp tile 32x64.
// cp.async 2-stage double buffer; Q output pre-scaled by 0.125*log2(e).
// ---------------------------------------------------------------------------
#define PJ_BK 32
#define PJ_NCH (DD / PJ_BK)     // 32
#define PJ_STAGE 32768
#define PJ_SMEM (2 * PJ_STAGE)  // 64KB

__device__ __forceinline__ void proj_load_stage(
    uint32_t sb, uint32_t stage_off,
    const __nv_bfloat16* __restrict__ Ah, const __nv_bfloat16* __restrict__ Al,
    const __nv_bfloat16* __restrict__ Bh, const __nv_bfloat16* __restrict__ Bl,
    int m0, int n0, int k0, int tid)
{
#pragma unroll
    for (int q = 0; q < 2; q++) {
        const int id = tid * 2 + q;
        const int row = id >> 2;
        const int ch = id & 3;
        const uint32_t so = stage_off + (uint32_t)(row * 64 + ((ch ^ ((row >> 1) & 3)) * 16));
        const size_t ga = (size_t)(m0 + row) * DD + k0 + ch * 8;
        const size_t gb = (size_t)(n0 + row) * DD + k0 + ch * 8;
        CP_ASYNC16(sb + so,          (const void*)(Ah + ga));
        CP_ASYNC16(sb + so + 8192,   (const void*)(Al + ga));
        CP_ASYNC16(sb + so + 16384,  (const void*)(Bh + gb));
        CP_ASYNC16(sb + so + 24576,  (const void*)(Bl + gb));
    }
}

__global__ __launch_bounds__(256, 2) void proj_mma(
    const float* __restrict__ bq, const float* __restrict__ bk, const float* __restrict__ bv)
{
    extern __shared__ char smraw[];
    const uint32_t sb = smem_u32(smraw);

    const int tid = threadIdx.x;
    const int wid = tid >> 5;
    const int lane = tid & 31;
    const int warp_m = wid & 3;
    const int warp_n = wid >> 2;
    const int which = blockIdx.z;
    const int n0 = blockIdx.x * 128;
    const int m0 = blockIdx.y * 128;

    const __nv_bfloat16* Ah = g_xhi + (size_t)which * MTOT * DD;
    const __nv_bfloat16* Al = g_xlo + (size_t)which * MTOT * DD;
    const __nv_bfloat16* Bh = g_whi + (size_t)which * DD * DD;
    const __nv_bfloat16* Bl = g_wlo + (size_t)which * DD * DD;
    const float* bias = (which == 0) ? bq : (which == 1) ? bk : bv;
    __nv_bfloat16* Yh = (which == 0) ? g_qh : (which == 1) ? g_kh : g_vh;
    __nv_bfloat16* Yl = (which == 0) ? g_ql : (which == 1) ? g_kl : g_vl;

    float acc[2][8][4];
#pragma unroll
    for (int t = 0; t < 2; t++)
#pragma unroll
        for (int j = 0; j < 8; j++)
#pragma unroll
            for (int c = 0; c < 4; c++) acc[t][j][c] = 0.0f;

    proj_load_stage(sb, 0,        Ah, Al, Bh, Bl, m0, n0, 0,     tid);
    CP_COMMIT();
    proj_load_stage(sb, PJ_STAGE, Ah, Al, Bh, Bl, m0, n0, PJ_BK, tid);
    CP_COMMIT();

    const int lrow = lane & 15;
    const int lkh = lane >> 4;

    for (int kt = 0; kt < PJ_NCH; kt++) {
        if (kt < PJ_NCH - 1) { CP_WAIT1(); } else { CP_WAIT0(); }
        __syncthreads();

        const uint32_t stg = sb + (uint32_t)((kt & 1) * PJ_STAGE);

#pragma unroll
        for (int ks = 0; ks < 2; ks++) {
            const int ch = ks * 2 + lkh;
            uint32_t ah[2][4], al[2][4], bh[4][4], bl[4][4];
#pragma unroll
            for (int t = 0; t < 2; t++) {
                const int ar = warp_m * 32 + t * 16 + lrow;
                const uint32_t aaddr = stg + (uint32_t)(ar * 64 + ((ch ^ ((ar >> 1) & 3)) * 16));
                LDM4(ah[t], aaddr);
                LDM4(al[t], aaddr + 8192);
            }
#pragma unroll
            for (int g = 0; g < 4; g++) {
                const int br = warp_n * 64 + g * 16 + lrow;
                const uint32_t baddr = stg + 16384u + (uint32_t)(br * 64 + ((ch ^ ((br >> 1) & 3)) * 16));
                LDM4(bh[g], baddr);
                LDM4(bl[g], baddr + 8192);
            }
#pragma unroll
            for (int t = 0; t < 2; t++)
#pragma unroll
                for (int g = 0; g < 4; g++) {
                    mma16816(acc[t][2 * g + 0], ah[t], bh[g][0], bh[g][2]);
                    mma16816(acc[t][2 * g + 1], ah[t], bh[g][1], bh[g][3]);
                    mma16816(acc[t][2 * g + 0], al[t], bh[g][0], bh[g][2]);
                    mma16816(acc[t][2 * g + 1], al[t], bh[g][1], bh[g][3]);
                    mma16816(acc[t][2 * g + 0], ah[t], bl[g][0], bl[g][2]);
                    mma16816(acc[t][2 * g + 1], ah[t], bl[g][1], bl[g][3]);
                }
        }

        __syncthreads();
        if (kt + 2 < PJ_NCH) {
            proj_load_stage(sb, (uint32_t)((kt & 1) * PJ_STAGE),
                            Ah, Al, Bh, Bl, m0, n0, (kt + 2) * PJ_BK, tid);
            CP_COMMIT();
        }
    }

    // Epilogue: add bias, (Q only) fold in softmax scale, split hi/lo, store.
    const float osc = (which == 0) ? 0.18033688f : 1.0f;   // 0.125 * log2(e)
    const int quad = lane >> 2;
    const int tpos = lane & 3;
#pragma unroll
    for (int t = 0; t < 2; t++) {
#pragma unroll
        for (int j = 0; j < 8; j++) {
            const int col = warp_n * 64 + j * 8 + tpos * 2;
            const float b0 = bias[n0 + col], b1 = bias[n0 + col + 1];
            const int r0 = m0 + warp_m * 32 + t * 16 + quad;
            const size_t i0 = (size_t)r0 * DD + n0 + col;
            const size_t i1 = (size_t)(r0 + 8) * DD + n0 + col;
            uint32_t lo;
            uint32_t hp = pack_split2((acc[t][j][0] + b0) * osc,
                                      (acc[t][j][1] + b1) * osc, lo);
            *(uint32_t*)(Yh + i0) = hp;
            *(uint32_t*)(Yl + i0) = lo;
            hp = pack_split2((acc[t][j][2] + b0) * osc,
                             (acc[t][j][3] + b1) * osc, lo);
            *(uint32_t*)(Yh + i1) = hp;
            *(uint32_t*)(Yl + i1) = lo;
        }
    }
}

// ---------------------------------------------------------------------------
// Tensor-core flash attention, bf16x3 both GEMMs (R7/R13-verified structure).
// CTA: 128 queries x one (b,h); 32 key-blocks of 64. 8 warps, warp = 16 rows.
// Q arrives pre-scaled by 0.125*log2(e) (folded into the projection).
// smem: Q hi/lo 32KB + 2 stages x (Khi,Klo,Vhi,Vlo 8KB each) = 96KB.
// ---------------------------------------------------------------------------
#define AT_NB 64
#define AT_NCH (SS / AT_NB)        // 32
#define AT_STAGE0 32768
#define AT_STG_SZ 32768
#define AT_SMEM (AT_STAGE0 + 2 * AT_STG_SZ)   // 98304

__device__ __forceinline__ void attn_load_kv(
    uint32_t sb, uint32_t stage_off, size_t kvbase, int kb0, int tid)
{
#pragma unroll
    for (int q = 0; q < 2; q++) {
        const int id = tid * 2 + q;            // 0..511
        const int row = id >> 3;               // 0..63
        const int ch = id & 7;
        const uint32_t so = stage_off + (uint32_t)(row * 128 + ((ch ^ (row & 7)) * 16));
        const size_t g = kvbase + (size_t)(kb0 + row) * DD + ch * 8;
        CP_ASYNC16(sb + so,          (const void*)(g_kh + g));
        CP_ASYNC16(sb + so + 8192,   (const void*)(g_kl + g));
        CP_ASYNC16(sb + so + 16384,  (const void*)(g_vh + g));
        CP_ASYNC16(sb + so + 24576,  (const void*)(g_vl + g));
    }
}

__global__ __launch_bounds__(256, 2) void attn_mma(float* __restrict__ out)
{
    extern __shared__ char smraw[];
    const uint32_t sb = smem_u32(smraw);

    const int tid = threadIdx.x;
    const int wid = tid >> 5;
    const int lane = tid & 31;
    const int quad = lane >> 2;
    const int tpos = lane & 3;
    const int lrow = lane & 15;
    const int lhal = lane >> 4;

    const int bh = blockIdx.y;
    const int b = bh >> 4;
    const int h = bh & 15;
    const int q0 = blockIdx.x * 128;

    const size_t qbase = ((size_t)(b * SS + q0)) * DD + h * HDIM;
    const size_t kvbase = ((size_t)b * SS) * DD + h * HDIM;

    // Q tile load (hi/lo), swizzled.
#pragma unroll
    for (int q = 0; q < 4; q++) {
        const int id = tid + q * 256;          // 0..1023
        const int row = id >> 3;               // 0..127
        const int ch = id & 7;
        const uint32_t so = (uint32_t)(row * 128 + ((ch ^ (row & 7)) * 16));
        const size_t g = qbase + (size_t)row * DD + ch * 8;
        CP_ASYNC16(sb + so,          (const void*)(g_qh + g));
        CP_ASYNC16(sb + 16384 + so,  (const void*)(g_ql + g));
    }
    attn_load_kv(sb, AT_STAGE0, kvbase, 0, tid);
    CP_COMMIT();                                // group 0: Q + KV0
    attn_load_kv(sb, AT_STAGE0 + AT_STG_SZ, kvbase, AT_NB, tid);
    CP_COMMIT();                                // group 1: KV1

    float oacc[8][4];
#pragma unroll
    for (int j = 0; j < 8; j++)
#pragma unroll
        for (int c = 0; c < 4; c++) oacc[j][c] = 0.0f;
    float mrow0 = -1e30f, mrow1 = -1e30f, lrow0 = 0.0f, lrow1 = 0.0f;

    for (int kt = 0; kt < AT_NCH; kt++) {
        if (kt < AT_NCH - 1) { CP_WAIT1(); } else { CP_WAIT0(); }
        __syncthreads();

        const uint32_t stg = sb + AT_STAGE0 + (uint32_t)((kt & 1) * AT_STG_SZ);

        // ---- S = Q K^T (M16 x N64 x K64 per warp), bf16x3 ----
        float sacc[8][4];
#pragma unroll
        for (int j = 0; j < 8; j++)
#pragma unroll
            for (int c = 0; c < 4; c++) sacc[j][c] = 0.0f;

#pragma unroll
        for (int ks = 0; ks < 4; ks++) {
            const int ch = 2 * ks + lhal;
            uint32_t ah[4], al[4];
            {
                const int ar = wid * 16 + lrow;
                const uint32_t aaddr = sb + (uint32_t)(ar * 128 + ((ch ^ (ar & 7)) * 16));
                LDM4(ah, aaddr);
                LDM4(al, aaddr + 16384);
            }
#pragma unroll
            for (int g = 0; g < 4; g++) {
                const int kr = g * 16 + lrow;
                const uint32_t baddr = stg + (uint32_t)(kr * 128 + ((ch ^ (kr & 7)) * 16));
                uint32_t bh4[4], bl4[4];
                LDM4(bh4, baddr);
                LDM4(bl4, baddr + 8192);
                mma16816(sacc[2 * g + 0], ah, bh4[0], bh4[2]);
                mma16816(sacc[2 * g + 1], ah, bh4[1], bh4[3]);
                mma16816(sacc[2 * g + 0], al, bh4[0], bh4[2]);
                mma16816(sacc[2 * g + 1], al, bh4[1], bh4[3]);
                mma16816(sacc[2 * g + 0], ah, bl4[0], bl4[2]);
                mma16816(sacc[2 * g + 1], ah, bl4[1], bl4[3]);
            }
        }

        // ---- online softmax (log2 domain; Q pre-scaled, rows quad / quad+8) ----
        float t0 = -1e30f, t1 = -1e30f;
#pragma unroll
        for (int j = 0; j < 8; j++) {
            t0 = fmaxf(t0, fmaxf(sacc[j][0], sacc[j][1]));
            t1 = fmaxf(t1, fmaxf(sacc[j][2], sacc[j][3]));
        }
        t0 = fmaxf(t0, __shfl_xor_sync(0xffffffffu, t0, 1));
        t0 = fmaxf(t0, __shfl_xor_sync(0xffffffffu, t0, 2));
        t1 = fmaxf(t1, __shfl_xor_sync(0xffffffffu, t1, 1));
        t1 = fmaxf(t1, __shfl_xor_sync(0xffffffffu, t1, 2));

        const float mn0 = fmaxf(mrow0, t0);
        const float mn1 = fmaxf(mrow1, t1);
        const float corr0 = ex2(mrow0 - mn0);
        const float corr1 = ex2(mrow1 - mn1);
        mrow0 = mn0; mrow1 = mn1;

        float rs0 = 0.0f, rs1 = 0.0f;
#pragma unroll
        for (int j = 0; j < 8; j++) {
            sacc[j][0] = ex2(sacc[j][0] - mn0);
            sacc[j][1] = ex2(sacc[j][1] - mn0);
            sacc[j][2] = ex2(sacc[j][2] - mn1);
            sacc[j][3] = ex2(sacc[j][3] - mn1);
            rs0 += sacc[j][0] + sacc[j][1];
            rs1 += sacc[j][2] + sacc[j][3];
        }
        rs0 += __shfl_xor_sync(0xffffffffu, rs0, 1);
        rs0 += __shfl_xor_sync(0xffffffffu, rs0, 2);
        rs1 += __shfl_xor_sync(0xffffffffu, rs1, 1);
        rs1 += __shfl_xor_sync(0xffffffffu, rs1, 2);
        lrow0 = lrow0 * corr0 + rs0;
        lrow1 = lrow1 * corr1 + rs1;

#pragma unroll
        for (int j = 0; j < 8; j++) {
            oacc[j][0] *= corr0; oacc[j][1] *= corr0;
            oacc[j][2] *= corr1; oacc[j][3] *= corr1;
        }

        // ---- O += P V (M16 x N64 x K64 per warp), bf16x3, P from registers ----
#pragma unroll
        for (int ks = 0; ks < 4; ks++) {
            uint32_t ph[4], pl[4];
            ph[0] = pack_split2(sacc[2 * ks][0],     sacc[2 * ks][1],     pl[0]);
            ph[1] = pack_split2(sacc[2 * ks][2],     sacc[2 * ks][3],     pl[1]);
            ph[2] = pack_split2(sacc[2 * ks + 1][0], sacc[2 * ks + 1][1], pl[2]);
            ph[3] = pack_split2(sacc[2 * ks + 1][2], sacc[2 * ks + 1][3], pl[3]);
#pragma unroll
            for (int g = 0; g < 4; g++) {
                const int vk = ks * 16 + lrow;
                const int cn = 2 * g + lhal;
                const uint32_t vaddr = stg + 16384u +
                    (uint32_t)(vk * 128 + ((cn ^ (vk & 7)) * 16));
                uint32_t vh4[4], vl4[4];
                LDM4T(vh4, vaddr);
                LDM4T(vl4, vaddr + 8192);
                mma16816(oacc[2 * g + 0], ph, vh4[0], vh4[1]);
                mma16816(oacc[2 * g + 1], ph, vh4[2], vh4[3]);
                mma16816(oacc[2 * g + 0], pl, vh4[0], vh4[1]);
                mma16816(oacc[2 * g + 1], pl, vh4[2], vh4[3]);
                mma16816(oacc[2 * g + 0], ph, vl4[0], vl4[1]);
                mma16816(oacc[2 * g + 1], ph, vl4[2], vl4[3]);
            }
        }

        __syncthreads();
        if (kt + 2 < AT_NCH) {
            attn_load_kv(sb, AT_STAGE0 + (uint32_t)((kt & 1) * AT_STG_SZ),
                         kvbase, (kt + 2) * AT_NB, tid);
            CP_COMMIT();
        }
    }

    // Epilogue: normalize, write [B,S,D]
    const float inv0 = 1.0f / lrow0;
    const float inv1 = 1.0f / lrow1;
    const int rowA = q0 + wid * 16 + quad;
#pragma unroll
    for (int j = 0; j < 8; j++) {
        const int col = h * HDIM + j * 8 + tpos * 2;
        *(float2*)(out + ((size_t)(b * SS + rowA)) * DD + col) =
            make_float2(oacc[j][0] * inv0, oacc[j][1] * inv0);
        *(float2*)(out + ((size_t)(b * SS + rowA + 8)) * DD + col) =
            make_float2(oacc[j][2] * inv1, oacc[j][3] * inv1);
    }
}

// ---------------------------------------------------------------------------
extern "C" void kernel_launch(void* const* d_in, const int* in_sizes, int n_in,
                              void* d_out, int out_size)
{
    (void)in_sizes; (void)n_in; (void)out_size;
    const float* query = (const float*)d_in[0];
    const float* key   = (const float*)d_in[1];
    const float* value = (const float*)d_in[2];
    const float* Wq    = (const float*)d_in[3];
    const float* bq    = (const float*)d_in[4];
    const float* Wk    = (const float*)d_in[5];
    const float* bk    = (const float*)d_in[6];
    const float* Wv    = (const float*)d_in[7];
    const float* bv    = (const float*)d_in[8];

    cudaFuncSetAttribute(proj_mma, cudaFuncAttributeMaxDynamicSharedMemorySize, PJ_SMEM);
    cudaFuncSetAttribute(attn_mma, cudaFuncAttributeMaxDynamicSharedMemorySize, AT_SMEM);

    convert_all<<<dim3(CVT_XBLK + CVT_WBLK, 1, 3), 256>>>(query, key, value, Wq, Wk, Wv);

    proj_mma<<<dim3(DD / 128, MTOT / 128, 3), 256, PJ_SMEM>>>(bq, bk, bv);

    attn_mma<<<dim3(SS / 128, BB * HH), 256, AT_SMEM>>>((float*)d_out);
}